// round 6
// baseline (speedup 1.0000x reference)
#include <cuda_runtime.h>

#define BH 32
#define L 2048
#define D 64
#define TQ 64              // query rows per block
#define TK 128             // keys per tile
#define NT (L / TK)        // 16
#define SROW 68            // K/V/Q smem row stride (17 float4, odd -> conflict-free)
#define PSROW 132          // p_s row stride (33 float4, odd)
#define WIN 2

typedef unsigned long long ull;

__device__ __forceinline__ void fma2(ull& d, ull a, ull b) {
    asm("fma.rn.f32x2 %0, %1, %2, %3;" : "=l"(d) : "l"(a), "l"(b), "l"(d));
}
__device__ __forceinline__ void mul2(ull& d, ull a) {
    asm("mul.rn.f32x2 %0, %1, %2;" : "=l"(d) : "l"(d), "l"(a));
}
__device__ __forceinline__ ull pk2(float lo, float hi) {
    ull r; asm("mov.b64 %0, {%1,%2};" : "=l"(r) : "f"(lo), "f"(hi)); return r;
}
__device__ __forceinline__ float lohi(ull a) {
    float lo, hi; asm("mov.b64 {%0,%1}, %2;" : "=f"(lo), "=f"(hi) : "l"(a));
    return lo + hi;
}
__device__ __forceinline__ void unpk(ull a, float& lo, float& hi) {
    asm("mov.b64 {%0,%1}, %2;" : "=f"(lo), "=f"(hi) : "l"(a));
}

// module-static scratch
__device__ int g_perm[BH][L];
__device__ int g_cnt[BH][2];
__device__ float g_out_scr[(size_t)BH * L * D];
__device__ float g_attn_scr[(size_t)BH * L * L];

// ---------------------------------------------------------------------------
// Kernel 0: zero the compaction counters
// ---------------------------------------------------------------------------
__global__ void gate_init() {
    int t = threadIdx.x;
    if (t < BH) { g_cnt[t][0] = 0; g_cnt[t][1] = 0; }
}

// ---------------------------------------------------------------------------
// Kernel 1: gate + compaction, 8 blocks per bh (1 row/thread).
// gate = sigmoid(q.w + b) > 0.5  <=>  q.w + b > 0
// ---------------------------------------------------------------------------
__global__ void __launch_bounds__(256)
gate_kernel(const float* __restrict__ q,
            const float* __restrict__ gw,
            const float* __restrict__ gb) {
    __shared__ float4 w_s[16];
    const int bh = blockIdx.x >> 3, seg = blockIdx.x & 7;
    const int t = threadIdx.x;
    if (t < 16) w_s[t] = ((const float4*)gw)[t];
    __syncthreads();
    const int r = seg * 256 + t;
    const float4* qr = (const float4*)(q + ((size_t)bh * L + r) * D);
    float s = gb[0];
#pragma unroll
    for (int c = 0; c < 16; c++) {
        float4 a = qr[c], w = w_s[c];
        s += a.x * w.x + a.y * w.y + a.z * w.z + a.w * w.w;
    }
    if (s > 0.f) g_perm[bh][atomicAdd(&g_cnt[bh][0], 1)] = r;
    else         g_perm[bh][L - 1 - atomicAdd(&g_cnt[bh][1], 1)] = r;
}

// ---------------------------------------------------------------------------
// Kernel 2: gated rows -> dense attention, fused single pass + in-block renorm.
// Block = 64 permuted query rows, 256 threads (8 warps).
// QK mapping: warp w owns rows w*8..w*8+7; lane j owns cols {j,j+32,j+64,j+96}.
// AV mapping: thread = (rowg = t>>4 -> rows rowg*4..+3) x (dg = t&15 -> dims dg*4..+3).
// Per tile: K->smem, QK (f32x2), stats (shfl), p->p_s, raw s->gmem, f->f_s,
//           rescale oacc, V->smem, AV (f32x2).
// End: out = oacc*inv; renorm sweep over raw scores (exp * inv) in-place.
// ---------------------------------------------------------------------------
__global__ void __launch_bounds__(256)
attn_gated(const float* __restrict__ q, const float* __restrict__ k,
           const float* __restrict__ v,
           float* attnp, float* outp) {
    extern __shared__ float smem[];
    float (*q_s)[SROW]  = (float(*)[SROW])smem;                          // 64 x 68
    float (*kv_s)[SROW] = (float(*)[SROW])(smem + TQ * SROW);            // 128 x 68
    float (*p_s)[PSROW] = (float(*)[PSROW])(smem + TQ * SROW + TK * SROW); // 64 x 132
    float* f_s    = smem + TQ * SROW + TK * SROW + TQ * PSROW;           // 64
    float* rinv_s = f_s + TQ;                                            // 64
    int*   rows_s = (int*)(rinv_s + TQ);                                 // 64

    float* attn = attnp ? attnp : g_attn_scr;
    float* out  = outp  ? outp  : g_out_scr;

    const int bh = blockIdx.y;
    const int ng = g_cnt[bh][0];
    const int base = (int)blockIdx.x * TQ;
    if (base >= ng) return;

    const int t = threadIdx.x;
    const int w = t >> 5, j = t & 31;
    const int qr0 = w * 8;            // QK rows for this warp
    const int rowg = t >> 4;          // AV row group (4 rows)
    const int dg = t & 15;            // AV dim group (float4)

    if (t < TQ) {
        int slot = base + t;
        rows_s[t] = g_perm[bh][slot < ng ? slot : ng - 1];
    }
    __syncthreads();

    // load Q tile: 64 rows x 16 float4
#pragma unroll
    for (int it = 0; it < 4; it++) {
        int idx = t + it * 256;
        int r = idx >> 4, c4 = idx & 15;
        float4 val = ((const float4*)(q + ((size_t)bh * L + rows_s[r]) * D))[c4];
        *(float4*)&q_s[r][c4 * 4] = val;
    }

    float m[8], ssum[8];
#pragma unroll
    for (int r = 0; r < 8; r++) { m[r] = -3.0e38f; ssum[r] = 0.f; }
    ull oacc[4][2];
#pragma unroll
    for (int rr = 0; rr < 4; rr++) { oacc[rr][0] = 0ull; oacc[rr][1] = 0ull; }

    for (int kt = 0; kt < NT; kt++) {
        __syncthreads();    // (a) prev AV done, kv_s free
        // load K tile: 128 rows x 16 float4
#pragma unroll
        for (int it = 0; it < 8; it++) {
            int idx = t + it * 256;
            int r = idx >> 4, c4 = idx & 15;
            float4 val = ((const float4*)(k + ((size_t)bh * L + kt * TK + r) * D))[c4];
            *(float4*)&kv_s[r][c4 * 4] = val;
        }
        __syncthreads();    // (b) K ready

        // ---- QK: 8 rows x 4 cols per thread, f32x2 ----
        ull acc[8][4];
#pragma unroll
        for (int r = 0; r < 8; r++)
#pragma unroll
            for (int c = 0; c < 4; c++) acc[r][c] = 0ull;

#pragma unroll
        for (int d4 = 0; d4 < 16; d4++) {
            ulonglong2 kvv[4];
#pragma unroll
            for (int c = 0; c < 4; c++) kvv[c] = ((const ulonglong2*)kv_s[j + 32 * c])[d4];
#pragma unroll
            for (int r = 0; r < 8; r++) {
                ulonglong2 qq = ((const ulonglong2*)q_s[qr0 + r])[d4];
#pragma unroll
                for (int c = 0; c < 4; c++) {
                    fma2(acc[r][c], qq.x, kvv[c].x);
                    fma2(acc[r][c], qq.y, kvv[c].y);
                }
            }
        }

        // ---- stats + p_s + raw scores ----
        float fexp[8];
#pragma unroll
        for (int r = 0; r < 8; r++) {
            float s0 = lohi(acc[r][0]) * 0.125f;
            float s1 = lohi(acc[r][1]) * 0.125f;
            float s2 = lohi(acc[r][2]) * 0.125f;
            float s3 = lohi(acc[r][3]) * 0.125f;
            float tm = fmaxf(fmaxf(s0, s1), fmaxf(s2, s3));
#pragma unroll
            for (int o = 16; o > 0; o >>= 1) tm = fmaxf(tm, __shfl_xor_sync(0xffffffffu, tm, o));
            float mn = fmaxf(m[r], tm);
            float p0 = __expf(s0 - mn), p1 = __expf(s1 - mn);
            float p2 = __expf(s2 - mn), p3 = __expf(s3 - mn);
            float part = p0 + p1 + p2 + p3;
#pragma unroll
            for (int o = 16; o > 0; o >>= 1) part += __shfl_xor_sync(0xffffffffu, part, o);
            fexp[r] = __expf(m[r] - mn);
            ssum[r] = ssum[r] * fexp[r] + part;
            m[r] = mn;
            float* pr = &p_s[qr0 + r][0];
            pr[j] = p0; pr[j + 32] = p1; pr[j + 64] = p2; pr[j + 96] = p3;
            if (base + qr0 + r < ng) {
                float* ap = attn + ((size_t)bh * L + rows_s[qr0 + r]) * (size_t)L + kt * TK;
                ap[j] = s0; ap[j + 32] = s1; ap[j + 64] = s2; ap[j + 96] = s3;
            }
        }
        if (j == 0) {
#pragma unroll
            for (int r = 0; r < 8; r++) f_s[qr0 + r] = fexp[r];
        }
        __syncthreads();    // (c) p_s/f_s ready; QK reads of kv_s done

        // rescale oacc; load V tile
#pragma unroll
        for (int rr = 0; rr < 4; rr++) {
            float f = f_s[rowg * 4 + rr];
            ull ff = pk2(f, f);
            mul2(oacc[rr][0], ff);
            mul2(oacc[rr][1], ff);
        }
#pragma unroll
        for (int it = 0; it < 8; it++) {
            int idx = t + it * 256;
            int r = idx >> 4, c4 = idx & 15;
            float4 val = ((const float4*)(v + ((size_t)bh * L + kt * TK + r) * D))[c4];
            *(float4*)&kv_s[r][c4 * 4] = val;
        }
        __syncthreads();    // (d) V ready

        // ---- AV: 4 rows x 4 dims per thread, f32x2 ----
#pragma unroll 8
        for (int c4 = 0; c4 < 32; c4++) {
            float4 pa[4];
#pragma unroll
            for (int rr = 0; rr < 4; rr++)
                pa[rr] = *(const float4*)&p_s[rowg * 4 + rr][c4 * 4];
#pragma unroll
            for (int e = 0; e < 4; e++) {
                ulonglong2 vv = ((const ulonglong2*)kv_s[c4 * 4 + e])[dg];
#pragma unroll
                for (int rr = 0; rr < 4; rr++) {
                    float pv = (e == 0) ? pa[rr].x : (e == 1) ? pa[rr].y : (e == 2) ? pa[rr].z : pa[rr].w;
                    ull pp = pk2(pv, pv);
                    fma2(oacc[rr][0], pp, vv.x);
                    fma2(oacc[rr][1], pp, vv.y);
                }
            }
        }
    }

    // per-row final inv for AV writer threads
    if (j == 0) {
#pragma unroll
        for (int r = 0; r < 8; r++) rinv_s[qr0 + r] = 1.0f / ssum[r];
    }
    __syncthreads();

    // ---- out = oacc * inv ----
#pragma unroll
    for (int rr = 0; rr < 4; rr++) {
        int row = rowg * 4 + rr;
        if (base + row < ng) {
            float inv = rinv_s[row];
            float4 o;
            unpk(oacc[rr][0], o.x, o.y);
            unpk(oacc[rr][1], o.z, o.w);
            o.x *= inv; o.y *= inv; o.z *= inv; o.w *= inv;
            ((float4*)(out + ((size_t)bh * L + rows_s[row]) * D))[dg] = o;
        }
    }

    // ---- renorm sweep: raw -> prob, in-place (warp owns its 8 QK rows) ----
#pragma unroll
    for (int r = 0; r < 8; r++) {
        if (base + qr0 + r >= ng) continue;
        float mm = m[r], inv = 1.0f / ssum[r];
        float4* ap = (float4*)(attn + ((size_t)bh * L + rows_s[qr0 + r]) * (size_t)L);
#pragma unroll 4
        for (int c4 = 0; c4 < 16; c4++) {
            int idx = c4 * 32 + j;
            float4 x = ap[idx];
            x.x = __expf(x.x - mm) * inv;
            x.y = __expf(x.y - mm) * inv;
            x.z = __expf(x.z - mm) * inv;
            x.w = __expf(x.w - mm) * inv;
            ap[idx] = x;
        }
    }
}

// ---------------------------------------------------------------------------
// Kernel 3: windowed rows — one warp per row. Exact fp32.
// ---------------------------------------------------------------------------
__global__ void __launch_bounds__(256)
attn_win(const float* __restrict__ q, const float* __restrict__ k,
         const float* __restrict__ v,
         float* attnp, float* outp) {
    float* attn = attnp ? attnp : g_attn_scr;
    float* out  = outp  ? outp  : g_out_scr;

    const int bh = blockIdx.y;
    const int nw = L - g_cnt[bh][0];
    const int widx = blockIdx.x * 8 + (threadIdx.x >> 5);
    if (widx >= nw) return;
    const int lane = threadIdx.x & 31;
    const int i = g_perm[bh][L - 1 - widx];
    const int j0 = max(0, i - WIN), j1 = min(L - 1, i + WIN);
    const int n = j1 - j0 + 1;

    const float* qr = q + ((size_t)bh * L + i) * D;
    float q0 = qr[lane], q1 = qr[lane + 32];

    float p[5];
    float mx = -3.0e38f;
#pragma unroll
    for (int jj = 0; jj < 5; jj++) {
        float sc = -3.0e38f;
        if (jj < n) {
            const float* kr = k + ((size_t)bh * L + j0 + jj) * D;
            float d = q0 * kr[lane] + q1 * kr[lane + 32];
#pragma unroll
            for (int o = 16; o > 0; o >>= 1) d += __shfl_xor_sync(0xffffffffu, d, o);
            sc = d * 0.125f;
        }
        p[jj] = sc;
        mx = fmaxf(mx, sc);
    }
    float sum = 0.f;
#pragma unroll
    for (int jj = 0; jj < 5; jj++) {
        p[jj] = (jj < n) ? __expf(p[jj] - mx) : 0.f;
        sum += p[jj];
    }
    float inv = 1.0f / sum;
#pragma unroll
    for (int jj = 0; jj < 5; jj++) p[jj] *= inv;

    // attn row: zeros except exact window probs
    float4* arow4 = (float4*)(attn + ((size_t)bh * L + i) * (size_t)L);
    const int s_lo = j0 >> 2, s_hi = j1 >> 2;
#pragma unroll
    for (int it = 0; it < 16; it++) {
        int s4 = lane + it * 32;
        if (s4 < s_lo || s4 > s_hi) arow4[s4] = make_float4(0.f, 0.f, 0.f, 0.f);
    }
    if (lane <= s_hi - s_lo) {
        int s4 = s_lo + lane;
        float vv[4];
#pragma unroll
        for (int e = 0; e < 4; e++) {
            int idx = s4 * 4 + e;
            vv[e] = (idx >= j0 && idx <= j1) ? p[idx - j0] : 0.f;
        }
        arow4[s4] = make_float4(vv[0], vv[1], vv[2], vv[3]);
    }

    // out
    float o0 = 0.f, o1 = 0.f;
#pragma unroll
    for (int jj = 0; jj < 5; jj++) {
        if (jj < n) {
            const float* vr = v + ((size_t)bh * L + j0 + jj) * D;
            o0 += p[jj] * vr[lane];
            o1 += p[jj] * vr[lane + 32];
        }
    }
    float* orow = out + ((size_t)bh * L + i) * D;
    orow[lane] = o0;
    orow[lane + 32] = o1;
}

// ---------------------------------------------------------------------------
extern "C" void kernel_launch(void* const* d_in, const int* in_sizes, int n_in,
                              void* d_out, int out_size) {
    const float* q  = (const float*)d_in[0];
    const float* k  = (const float*)d_in[1];
    const float* v  = (const float*)d_in[2];
    const float* gw = (const float*)d_in[3];
    const float* gb = (const float*)d_in[4];

    const long long OUTE = (long long)BH * L * D;        // 4194304
    const long long ATTE = (long long)BH * L * L;        // 134217728

    float* outp = nullptr;
    float* attnp = nullptr;
    if ((long long)out_size == OUTE + ATTE) {
        outp = (float*)d_out;
        attnp = (float*)d_out + OUTE;
    } else if ((long long)out_size == ATTE) {
        attnp = (float*)d_out;          // out -> device scratch
    } else {
        outp = (float*)d_out;           // attn -> device scratch
    }

    const int SMEMB = (TQ * SROW + TK * SROW + TQ * PSROW + 2 * TQ) * 4 + TQ * 4 + 256;
    // Set once per call; persists across calls (first call is outside capture).
    cudaFuncSetAttribute(attn_gated, cudaFuncAttributeMaxDynamicSharedMemorySize, SMEMB);

    gate_init<<<1, 64>>>();
    gate_kernel<<<BH * 8, 256>>>(q, gw, gb);
    attn_gated<<<dim3(L / TQ, BH), 256, SMEMB>>>(q, k, v, attnp, outp);
    attn_win<<<dim3(L / 8, BH), 256>>>(q, k, v, attnp, outp);
}

// round 8
// speedup vs baseline: 1.1278x; 1.1278x over previous
#include <cuda_runtime.h>
#include <cstdint>

#define BH 32
#define L 2048
#define D 64
#define TQ 128
#define TK 128
#define NTILE (L / TK)
#define WIN 2

#define QOFF 1024
#define KOFF (QOFF + 65536)
#define VOFF (KOFF + 65536)
#define SMEMB (VOFF + 32768)

__device__ __forceinline__ uint32_t rna(float x) {
    uint32_t r; asm("cvt.rna.tf32.f32 %0, %1;" : "=r"(r) : "f"(x)); return r;
}
__device__ __forceinline__ void mma8(float* d, uint32_t a0, uint32_t a1, uint32_t a2, uint32_t a3,
                                     uint32_t b0, uint32_t b1) {
    asm volatile("mma.sync.aligned.m16n8k8.row.col.f32.tf32.tf32.f32 "
        "{%0,%1,%2,%3}, {%4,%5,%6,%7}, {%8,%9}, {%0,%1,%2,%3};"
        : "+f"(d[0]), "+f"(d[1]), "+f"(d[2]), "+f"(d[3])
        : "r"(a0), "r"(a1), "r"(a2), "r"(a3), "r"(b0), "r"(b1));
}

__device__ int g_perm[BH][L];
__device__ int g_cnt[BH][2];
__device__ float g_out_scr[(size_t)BH * L * D];
__device__ float g_attn_scr[(size_t)BH * L * L];

// ---------------------------------------------------------------------------
__global__ void gate_init() {
    int t = threadIdx.x;
    if (t < BH) { g_cnt[t][0] = 0; g_cnt[t][1] = 0; }
}

__global__ void __launch_bounds__(256)
gate_kernel(const float* __restrict__ q, const float* __restrict__ gw, const float* __restrict__ gb) {
    __shared__ float4 w_s[16];
    const int bh = blockIdx.x >> 3, seg = blockIdx.x & 7;
    const int t = threadIdx.x;
    if (t < 16) w_s[t] = ((const float4*)gw)[t];
    __syncthreads();
    const int r = seg * 256 + t;
    const float4* qr = (const float4*)(q + ((size_t)bh * L + r) * D);
    float s = gb[0];
#pragma unroll
    for (int c = 0; c < 16; c++) {
        float4 a = qr[c], w = w_s[c];
        s += a.x * w.x + a.y * w.y + a.z * w.z + a.w * w.w;
    }
    if (s > 0.f) g_perm[bh][atomicAdd(&g_cnt[bh][0], 1)] = r;
    else         g_perm[bh][L - 1 - atomicAdd(&g_cnt[bh][1], 1)] = r;
}

// ---------------------------------------------------------------------------
// gated rows: two-pass tf32 mma.sync attention.
// Warp w owns rows 16w..16w+15; lane (g = lane>>2, tg = lane&3).
// ---------------------------------------------------------------------------
__global__ void __launch_bounds__(256, 1)
attn_gated(const float* __restrict__ q, const float* __restrict__ k,
           const float* __restrict__ v, float* attnp, float* outp) {
    extern __shared__ __align__(16) char sm[];
    float* attn = attnp ? attnp : g_attn_scr;
    float* out  = outp  ? outp  : g_out_scr;
    const int bh = blockIdx.y;
    const int ng = g_cnt[bh][0];
    const int base = (int)blockIdx.x * TQ;
    if (base >= ng) return;

    const int t = threadIdx.x, w = t >> 5, lane = t & 31;
    const int g = lane >> 2, tg = lane & 3;
    int* rows_s = (int*)sm;

    if (t < TQ) { int s = base + t; rows_s[t] = g_perm[bh][s < ng ? s : ng - 1]; }
    __syncthreads();

    // ---- stage Q (x 1/8, tf32 hi/lo, A-fragment packed) ----
#pragma unroll
    for (int it = 0; it < 8; it++) {
        int idx = t + it * 256;
        int r = idx >> 4, c4 = idx & 15;
        float4 val = ((const float4*)(q + ((size_t)bh * L + rows_s[r]) * D))[c4];
        float f[4] = {val.x * .125f, val.y * .125f, val.z * .125f, val.w * .125f};
        int wt = r >> 4, rw = r & 15, gg = rw & 7, hi8 = rw >> 3;
        int ks = c4 >> 1, half = c4 & 1;
        char* bp = sm + QOFF + ((wt * 8 + ks) << 10) + ((half * 2 + hi8) << 2);
#pragma unroll
        for (int e = 0; e < 4; e++) {
            uint32_t h = rna(f[e]);
            uint32_t l = rna(f[e] - __uint_as_float(h));
            char* p = bp + ((gg * 4 + e) << 5);
            *(uint32_t*)p = h;
            *(uint32_t*)(p + 16) = l;
        }
    }
    __syncthreads();

    // A fragments (persist across both passes)
    uint4 qh4[8], ql4[8];
#pragma unroll
    for (int ks = 0; ks < 8; ks++) {
        qh4[ks] = *(const uint4*)(sm + QOFF + ((w * 8 + ks) << 10) + (lane << 5));
        ql4[ks] = *(const uint4*)(sm + QOFF + ((w * 8 + ks) << 10) + (lane << 5) + 16);
    }

    // ---------------- Pass A: row sums (1-combo QK) ----------------
    float sum0 = 0.f, sum8 = 0.f;
    for (int kt = 0; kt < NTILE; kt++) {
        __syncthreads();
        const float* kg = k + ((size_t)bh * L + kt * TK) * D;
#pragma unroll
        for (int it = 0; it < 8; it++) {
            int idx = t + it * 256;
            int key = idx >> 4, c4 = idx & 15;
            float4 val = ((const float4*)(kg + (size_t)key * D))[c4];
            float f[4] = {val.x, val.y, val.z, val.w};
            int nt = key >> 3, gg = key & 7, ks = c4 >> 1, half = c4 & 1;
            char* bp = sm + KOFF + ((nt * 8 + ks) << 9) + (half << 2);
#pragma unroll
            for (int e = 0; e < 4; e++) {
                uint32_t h = rna(f[e]);
                uint32_t l = rna(f[e] - __uint_as_float(h));
                char* p = bp + ((gg * 4 + e) << 4);
                *(uint32_t*)p = h;
                *(uint32_t*)(p + 8) = l;
            }
        }
        __syncthreads();
        for (int nt = 0; nt < 16; nt++) {
            float dd[4] = {0.f, 0.f, 0.f, 0.f};
#pragma unroll
            for (int ks = 0; ks < 8; ks++) {
                uint2 kk = *(const uint2*)(sm + KOFF + ((nt * 8 + ks) << 9) + (lane << 4));
                mma8(dd, qh4[ks].x, qh4[ks].y, qh4[ks].z, qh4[ks].w, kk.x, kk.y);
            }
            sum0 += __expf(dd[0]) + __expf(dd[1]);
            sum8 += __expf(dd[2]) + __expf(dd[3]);
        }
    }
    sum0 += __shfl_xor_sync(0xffffffffu, sum0, 1);
    sum0 += __shfl_xor_sync(0xffffffffu, sum0, 2);
    sum8 += __shfl_xor_sync(0xffffffffu, sum8, 1);
    sum8 += __shfl_xor_sync(0xffffffffu, sum8, 2);
    const float inv0 = 1.f / sum0, inv8 = 1.f / sum8;

    // ---------------- Pass B: probs + AV (3-combo QK, 1-combo AV) ----------------
    const int rb0 = w * 16 + g;
    const bool vr0 = base + rb0 < ng, vr8 = base + rb0 + 8 < ng;
    float* arow0 = attn + ((size_t)bh * L + rows_s[rb0]) * (size_t)L;
    float* arow8 = attn + ((size_t)bh * L + rows_s[rb0 + 8]) * (size_t)L;
    float avD[8][4];
#pragma unroll
    for (int i = 0; i < 8; i++) { avD[i][0] = avD[i][1] = avD[i][2] = avD[i][3] = 0.f; }

    const int src0 = (lane & 28) | (tg >> 1);
    const int src2 = src0 + 2;
    const bool odd = tg & 1;

    for (int kt = 0; kt < NTILE; kt++) {
        __syncthreads();
        const float* kg = k + ((size_t)bh * L + kt * TK) * D;
        const float* vg = v + ((size_t)bh * L + kt * TK) * D;
#pragma unroll
        for (int it = 0; it < 8; it++) {
            int idx = t + it * 256;
            int key = idx >> 4, c4 = idx & 15;
            float4 val = ((const float4*)(kg + (size_t)key * D))[c4];
            float f[4] = {val.x, val.y, val.z, val.w};
            int nt = key >> 3, gg = key & 7, ks = c4 >> 1, half = c4 & 1;
            char* bp = sm + KOFF + ((nt * 8 + ks) << 9) + (half << 2);
#pragma unroll
            for (int e = 0; e < 4; e++) {
                uint32_t h = rna(f[e]);
                uint32_t l = rna(f[e] - __uint_as_float(h));
                char* p = bp + ((gg * 4 + e) << 4);
                *(uint32_t*)p = h;
                *(uint32_t*)(p + 8) = l;
            }
        }
#pragma unroll
        for (int it = 0; it < 8; it++) {
            int idx = t + it * 256;
            int key = idx >> 4, c4 = idx & 15;
            float4 val = ((const float4*)(vg + (size_t)key * D))[c4];
            float f[4] = {val.x, val.y, val.z, val.w};
            int ttg = key & 3, half = (key >> 2) & 1, ks = key >> 3;
            char* bp = sm + VOFF + (ks << 8) + (ttg << 3) + (half << 2);
#pragma unroll
            for (int e = 0; e < 4; e++) {
                int dim = c4 * 4 + e;
                *(uint32_t*)(bp + ((dim >> 3) << 12) + ((dim & 7) << 5)) = rna(f[e]);
            }
        }
        __syncthreads();

        for (int nt = 0; nt < 16; nt++) {
            float dd[4] = {0.f, 0.f, 0.f, 0.f};
#pragma unroll
            for (int ks = 0; ks < 8; ks++) {
                uint4 kk = *(const uint4*)(sm + KOFF + ((nt * 8 + ks) << 9) + (lane << 4));
                mma8(dd, qh4[ks].x, qh4[ks].y, qh4[ks].z, qh4[ks].w, kk.x, kk.y);
                mma8(dd, qh4[ks].x, qh4[ks].y, qh4[ks].z, qh4[ks].w, kk.z, kk.w);
                mma8(dd, ql4[ks].x, ql4[ks].y, ql4[ks].z, ql4[ks].w, kk.x, kk.y);
            }
            float p0 = __expf(dd[0]) * inv0, p1 = __expf(dd[1]) * inv0;
            float p2 = __expf(dd[2]) * inv8, p3 = __expf(dd[3]) * inv8;
            int co = kt * TK + nt * 8 + 2 * tg;
            if (vr0) *(float2*)(arow0 + co) = make_float2(p0, p1);
            if (vr8) *(float2*)(arow8 + co) = make_float2(p2, p3);
            uint32_t h0 = rna(p0), h1 = rna(p1), h2 = rna(p2), h3 = rna(p3);
            uint32_t x00 = __shfl_sync(0xffffffffu, h0, src0), x01 = __shfl_sync(0xffffffffu, h1, src0);
            uint32_t x20 = __shfl_sync(0xffffffffu, h2, src0), x21 = __shfl_sync(0xffffffffu, h3, src0);
            uint32_t y00 = __shfl_sync(0xffffffffu, h0, src2), y01 = __shfl_sync(0xffffffffu, h1, src2);
            uint32_t y20 = __shfl_sync(0xffffffffu, h2, src2), y21 = __shfl_sync(0xffffffffu, h3, src2);
            uint32_t a0 = odd ? x01 : x00, a1 = odd ? x21 : x20;
            uint32_t a2 = odd ? y01 : y00, a3 = odd ? y21 : y20;
#pragma unroll
            for (int ntd = 0; ntd < 8; ntd++) {
                uint2 vv = *(const uint2*)(sm + VOFF + ((ntd * 16 + nt) << 8) + (lane << 3));
                mma8(avD[ntd], a0, a1, a2, a3, vv.x, vv.y);
            }
        }
    }

    float* orow0 = out + ((size_t)bh * L + rows_s[rb0]) * D;
    float* orow8 = out + ((size_t)bh * L + rows_s[rb0 + 8]) * D;
#pragma unroll
    for (int ntd = 0; ntd < 8; ntd++) {
        int dc = ntd * 8 + 2 * tg;
        if (vr0) *(float2*)(orow0 + dc) = make_float2(avD[ntd][0], avD[ntd][1]);
        if (vr8) *(float2*)(orow8 + dc) = make_float2(avD[ntd][2], avD[ntd][3]);
    }
}

// ---------------------------------------------------------------------------
__global__ void __launch_bounds__(256)
attn_win(const float* __restrict__ q, const float* __restrict__ k,
         const float* __restrict__ v, float* attnp, float* outp) {
    float* attn = attnp ? attnp : g_attn_scr;
    float* out  = outp  ? outp  : g_out_scr;
    const int bh = blockIdx.y;
    const int nw = L - g_cnt[bh][0];
    const int widx = blockIdx.x * 8 + (threadIdx.x >> 5);
    if (widx >= nw) return;
    const int lane = threadIdx.x & 31;
    const int i = g_perm[bh][L - 1 - widx];
    const int j0 = max(0, i - WIN), j1 = min(L - 1, i + WIN);
    const int n = j1 - j0 + 1;
    const float* qr = q + ((size_t)bh * L + i) * D;
    float q0 = qr[lane], q1 = qr[lane + 32];
    float p[5], mx = -3.0e38f;
#pragma unroll
    for (int jj = 0; jj < 5; jj++) {
        float sc = -3.0e38f;
        if (jj < n) {
            const float* kr = k + ((size_t)bh * L + j0 + jj) * D;
            float d = q0 * kr[lane] + q1 * kr[lane + 32];
#pragma unroll
            for (int o = 16; o > 0; o >>= 1) d += __shfl_xor_sync(0xffffffffu, d, o);
            sc = d * 0.125f;
        }
        p[jj] = sc; mx = fmaxf(mx, sc);
    }
    float sum = 0.f;
#pragma unroll
    for (int jj = 0; jj < 5; jj++) { p[jj] = (jj < n) ? __expf(p[jj] - mx) : 0.f; sum += p[jj]; }
    float inv = 1.0f / sum;
#pragma unroll
    for (int jj = 0; jj < 5; jj++) p[jj] *= inv;

    float4* arow4 = (float4*)(attn + ((size_t)bh * L + i) * (size_t)L);
    const int s_lo = j0 >> 2, s_hi = j1 >> 2;
#pragma unroll
    for (int it = 0; it < 16; it++) {
        int s4 = lane + it * 32;
        if (s4 < s_lo || s4 > s_hi) arow4[s4] = make_float4(0.f, 0.f, 0.f, 0.f);
    }
    if (lane <= s_hi - s_lo) {
        int s4 = s_lo + lane;
        float vv[4];
#pragma unroll
        for (int e = 0; e < 4; e++) {
            int idx = s4 * 4 + e;
            vv[e] = (idx >= j0 && idx <= j1) ? p[idx - j0] : 0.f;
        }
        arow4[s4] = make_float4(vv[0], vv[1], vv[2], vv[3]);
    }
    float o0 = 0.f, o1 = 0.f;
#pragma unroll
    for (int jj = 0; jj < 5; jj++) {
        if (jj < n) {
            const float* vr = v + ((size_t)bh * L + j0 + jj) * D;
            o0 += p[jj] * vr[lane];
            o1 += p[jj] * vr[lane + 32];
        }
    }
    float* orow = out + ((size_t)bh * L + i) * D;
    orow[lane] = o0; orow[lane + 32] = o1;
}

// ---------------------------------------------------------------------------
extern "C" void kernel_launch(void* const* d_in, const int* in_sizes, int n_in,
                              void* d_out, int out_size) {
    const float* q  = (const float*)d_in[0];
    const float* k  = (const float*)d_in[1];
    const float* v  = (const float*)d_in[2];
    const float* gw = (const float*)d_in[3];
    const float* gb = (const float*)d_in[4];

    const long long OUTE = (long long)BH * L * D;
    const long long ATTE = (long long)BH * L * L;
    float* outp = nullptr; float* attnp = nullptr;
    if ((long long)out_size == OUTE + ATTE) { outp = (float*)d_out; attnp = (float*)d_out + OUTE; }
    else if ((long long)out_size == ATTE)   { attnp = (float*)d_out; }
    else                                    { outp = (float*)d_out; }

    cudaFuncSetAttribute(attn_gated, cudaFuncAttributeMaxDynamicSharedMemorySize, SMEMB);
    gate_init<<<1, 64>>>();
    gate_kernel<<<BH * 8, 256>>>(q, gw, gb);
    attn_gated<<<dim3(L / TQ, BH), 256, SMEMB>>>(q, k, v, attnp, outp);
    attn_win<<<dim3(L / 8, BH), 256>>>(q, k, v, attnp, outp);
}

// round 10
// speedup vs baseline: 2.4417x; 2.1650x over previous
#include <cuda_runtime.h>
#include <cstdint>

#define BH 32
#define L 2048
#define D 64
#define TQ 128
#define TK 128
#define NTILE (L / TK)
#define WIN 2

#define KOFF 1024
#define KBLK 272                 // K/V (nt*8+ks) block stride: 256B data + 16B pad
#define QBLK 528                 // Q A-frag block stride: 512B data + 16B pad
#define VOFF (KOFF + 128 * KBLK) // 35840
#define VNTD 4368                // ntd stride: 16*272 + 16
#define SMEMB (VOFF + 8 * VNTD)  // 70784

__device__ __forceinline__ uint32_t rna(float x) {
    uint32_t r; asm("cvt.rna.tf32.f32 %0, %1;" : "=r"(r) : "f"(x)); return r;
}
__device__ __forceinline__ void mma8(float* d, uint32_t a0, uint32_t a1, uint32_t a2, uint32_t a3,
                                     uint32_t b0, uint32_t b1) {
    asm volatile("mma.sync.aligned.m16n8k8.row.col.f32.tf32.tf32.f32 "
        "{%0,%1,%2,%3}, {%4,%5,%6,%7}, {%8,%9}, {%0,%1,%2,%3};"
        : "+f"(d[0]), "+f"(d[1]), "+f"(d[2]), "+f"(d[3])
        : "r"(a0), "r"(a1), "r"(a2), "r"(a3), "r"(b0), "r"(b1));
}

__device__ int g_perm[BH][L];
__device__ int g_cnt[BH][2];
__device__ float g_out_scr[(size_t)BH * L * D];
__device__ float g_attn_scr[(size_t)BH * L * L];

// ---------------------------------------------------------------------------
__global__ void gate_init() {
    int t = threadIdx.x;
    if (t < BH) { g_cnt[t][0] = 0; g_cnt[t][1] = 0; }
}

__global__ void __launch_bounds__(256)
gate_kernel(const float* __restrict__ q, const float* __restrict__ gw, const float* __restrict__ gb) {
    __shared__ float4 w_s[16];
    const int bh = blockIdx.x >> 3, seg = blockIdx.x & 7;
    const int t = threadIdx.x;
    if (t < 16) w_s[t] = ((const float4*)gw)[t];
    __syncthreads();
    const int r = seg * 256 + t;
    const float4* qr = (const float4*)(q + ((size_t)bh * L + r) * D);
    float s = gb[0];
#pragma unroll
    for (int c = 0; c < 16; c++) {
        float4 a = qr[c], w = w_s[c];
        s += a.x * w.x + a.y * w.y + a.z * w.z + a.w * w.w;
    }
    if (s > 0.f) g_perm[bh][atomicAdd(&g_cnt[bh][0], 1)] = r;
    else         g_perm[bh][L - 1 - atomicAdd(&g_cnt[bh][1], 1)] = r;
}

// ---------------------------------------------------------------------------
// stage one K tile (128 keys x 64 dims) as tf32-hi B-fragments.
// unit = (key, ks): 2 LDG.128 -> 2 STS.128. Layout: [(nt*8+ks)*KBLK][gg*32].
// ---------------------------------------------------------------------------
__device__ __forceinline__ void stage_k(const float* __restrict__ kg, char* sm, int t) {
#pragma unroll
    for (int it = 0; it < 4; it++) {
        int u = t + it * 256;
        int ks = u & 7, key = u >> 3;
        const float4* kr = (const float4*)(kg + (size_t)key * D);
        float4 a = kr[2 * ks], b = kr[2 * ks + 1];
        int nt = key >> 3, gg = key & 7;
        char* bp = sm + KOFF + (nt * 8 + ks) * KBLK + gg * 32;
        uint4 w0 = make_uint4(rna(a.x), rna(b.x), rna(a.y), rna(b.y));
        uint4 w1 = make_uint4(rna(a.z), rna(b.z), rna(a.w), rna(b.w));
        *(uint4*)bp = w0;
        *(uint4*)(bp + 16) = w1;
    }
}

// ---------------------------------------------------------------------------
// gated rows: two-pass tf32 mma.sync attention (1-combo QK, 1-combo AV).
// Warp w owns rows 16w..16w+15; lane: g = lane>>2, tg = lane&3.
// ---------------------------------------------------------------------------
__global__ void __launch_bounds__(256, 2)
attn_gated(const float* __restrict__ q, const float* __restrict__ k,
           const float* __restrict__ v, float* attnp, float* outp) {
    extern __shared__ __align__(16) char sm[];
    float* attn = attnp ? attnp : g_attn_scr;
    float* out  = outp  ? outp  : g_out_scr;
    const int bh = blockIdx.y;
    const int ng = g_cnt[bh][0];
    const int base = (int)blockIdx.x * TQ;
    if (base >= ng) return;

    const int t = threadIdx.x, w = t >> 5, lane = t & 31;
    const int g = lane >> 2, tg = lane & 3;
    int* rows_s = (int*)sm;

    if (t < TQ) { int s = base + t; rows_s[t] = g_perm[bh][s < ng ? s : ng - 1]; }
    __syncthreads();

    // ---- stage Q A-frags (x 1/8, tf32 hi) into K region with QBLK stride ----
    // unit u: ks = u&7, rp = (u>>3)&7, wt = u>>6. Block (wt*8+ks): 512B of frags.
#pragma unroll
    for (int it = 0; it < 2; it++) {
        int u = t + it * 256;
        int ks = u & 7, rp = (u >> 3) & 7, wt = u >> 6;
        int r0 = wt * 16 + rp, r1 = r0 + 8;
        const float4* q0 = (const float4*)(q + ((size_t)bh * L + rows_s[r0]) * D);
        const float4* q1 = (const float4*)(q + ((size_t)bh * L + rows_s[r1]) * D);
        float4 a0 = q0[2 * ks], a1 = q0[2 * ks + 1];
        float4 b0 = q1[2 * ks], b1 = q1[2 * ks + 1];
        char* bp = sm + KOFF + (wt * 8 + ks) * QBLK + rp * 64;
        *(uint4*)bp        = make_uint4(rna(a0.x * .125f), rna(b0.x * .125f), rna(a1.x * .125f), rna(b1.x * .125f));
        *(uint4*)(bp + 16) = make_uint4(rna(a0.y * .125f), rna(b0.y * .125f), rna(a1.y * .125f), rna(b1.y * .125f));
        *(uint4*)(bp + 32) = make_uint4(rna(a0.z * .125f), rna(b0.z * .125f), rna(a1.z * .125f), rna(b1.z * .125f));
        *(uint4*)(bp + 48) = make_uint4(rna(a0.w * .125f), rna(b0.w * .125f), rna(a1.w * .125f), rna(b1.w * .125f));
    }
    __syncthreads();

    uint4 qh4[8];
#pragma unroll
    for (int ks = 0; ks < 8; ks++)
        qh4[ks] = *(const uint4*)(sm + KOFF + (w * 8 + ks) * QBLK + lane * 16);
    __syncthreads();   // all qh4 loads done before pass A overwrites the region

    // ---------------- Pass A: row sums ----------------
    float sum0 = 0.f, sum8 = 0.f;
    for (int kt = 0; kt < NTILE; kt++) {
        __syncthreads();
        stage_k(k + ((size_t)bh * L + kt * TK) * D, sm, t);
        __syncthreads();
        for (int nt = 0; nt < 16; nt++) {
            float dd[4] = {0.f, 0.f, 0.f, 0.f};
#pragma unroll
            for (int ks = 0; ks < 8; ks++) {
                uint2 kk = *(const uint2*)(sm + KOFF + (nt * 8 + ks) * KBLK + lane * 8);
                mma8(dd, qh4[ks].x, qh4[ks].y, qh4[ks].z, qh4[ks].w, kk.x, kk.y);
            }
            sum0 += __expf(dd[0]) + __expf(dd[1]);
            sum8 += __expf(dd[2]) + __expf(dd[3]);
        }
    }
    sum0 += __shfl_xor_sync(0xffffffffu, sum0, 1);
    sum0 += __shfl_xor_sync(0xffffffffu, sum0, 2);
    sum8 += __shfl_xor_sync(0xffffffffu, sum8, 1);
    sum8 += __shfl_xor_sync(0xffffffffu, sum8, 2);
    const float inv0 = 1.f / sum0, inv8 = 1.f / sum8;

    // ---------------- Pass B: probs + AV ----------------
    const int rb0 = w * 16 + g;
    const bool vr0 = base + rb0 < ng, vr8 = base + rb0 + 8 < ng;
    float* arow0 = attn + ((size_t)bh * L + rows_s[rb0]) * (size_t)L;
    float* arow8 = attn + ((size_t)bh * L + rows_s[rb0 + 8]) * (size_t)L;
    float avD[8][4];
#pragma unroll
    for (int i = 0; i < 8; i++) { avD[i][0] = avD[i][1] = avD[i][2] = avD[i][3] = 0.f; }

    const int src0 = (lane & 28) | (tg >> 1);
    const int src2 = src0 + 2;
    const bool odd = tg & 1;

    for (int kt = 0; kt < NTILE; kt++) {
        __syncthreads();
        stage_k(k + ((size_t)bh * L + kt * TK) * D, sm, t);
        {   // stage V: unit = (key-pair, c4): 2 LDG.128 -> 4 STS.64
            const float* vg = v + ((size_t)bh * L + kt * TK) * D;
#pragma unroll
            for (int it = 0; it < 4; it++) {
                int u = t + it * 256;
                int c4 = u & 15, pr = u >> 4;
                int nt = pr >> 2, ttg = pr & 3;
                int key0 = nt * 8 + ttg;
                float4 v0 = ((const float4*)(vg + (size_t)key0 * D))[c4];
                float4 v1 = ((const float4*)(vg + (size_t)(key0 + 4) * D))[c4];
                int d0 = 4 * c4;
                int ntd = d0 >> 3, g0 = d0 & 7;
                char* bp = sm + VOFF + ntd * VNTD + nt * KBLK + ttg * 8;
                *(uint2*)(bp + (g0 + 0) * 32) = make_uint2(rna(v0.x), rna(v1.x));
                *(uint2*)(bp + (g0 + 1) * 32) = make_uint2(rna(v0.y), rna(v1.y));
                *(uint2*)(bp + (g0 + 2) * 32) = make_uint2(rna(v0.z), rna(v1.z));
                *(uint2*)(bp + (g0 + 3) * 32) = make_uint2(rna(v0.w), rna(v1.w));
            }
        }
        __syncthreads();

        for (int nt = 0; nt < 16; nt++) {
            float dd[4] = {0.f, 0.f, 0.f, 0.f};
#pragma unroll
            for (int ks = 0; ks < 8; ks++) {
                uint2 kk = *(const uint2*)(sm + KOFF + (nt * 8 + ks) * KBLK + lane * 8);
                mma8(dd, qh4[ks].x, qh4[ks].y, qh4[ks].z, qh4[ks].w, kk.x, kk.y);
            }
            float p0 = __expf(dd[0]) * inv0, p1 = __expf(dd[1]) * inv0;
            float p2 = __expf(dd[2]) * inv8, p3 = __expf(dd[3]) * inv8;
            int co = kt * TK + nt * 8 + 2 * tg;
            if (vr0) *(float2*)(arow0 + co) = make_float2(p0, p1);
            if (vr8) *(float2*)(arow8 + co) = make_float2(p2, p3);
            uint32_t h0 = rna(p0), h1 = rna(p1), h2 = rna(p2), h3 = rna(p3);
            uint32_t x00 = __shfl_sync(0xffffffffu, h0, src0), x01 = __shfl_sync(0xffffffffu, h1, src0);
            uint32_t x20 = __shfl_sync(0xffffffffu, h2, src0), x21 = __shfl_sync(0xffffffffu, h3, src0);
            uint32_t y00 = __shfl_sync(0xffffffffu, h0, src2), y01 = __shfl_sync(0xffffffffu, h1, src2);
            uint32_t y20 = __shfl_sync(0xffffffffu, h2, src2), y21 = __shfl_sync(0xffffffffu, h3, src2);
            uint32_t a0 = odd ? x01 : x00, a1 = odd ? x21 : x20;
            uint32_t a2 = odd ? y01 : y00, a3 = odd ? y21 : y20;
#pragma unroll
            for (int ntd = 0; ntd < 8; ntd++) {
                uint2 vv = *(const uint2*)(sm + VOFF + ntd * VNTD + nt * KBLK + lane * 8);
                mma8(avD[ntd], a0, a1, a2, a3, vv.x, vv.y);
            }
        }
    }

    float* orow0 = out + ((size_t)bh * L + rows_s[rb0]) * D;
    float* orow8 = out + ((size_t)bh * L + rows_s[rb0 + 8]) * D;
#pragma unroll
    for (int ntd = 0; ntd < 8; ntd++) {
        int dc = ntd * 8 + 2 * tg;
        if (vr0) *(float2*)(orow0 + dc) = make_float2(avD[ntd][0], avD[ntd][1]);
        if (vr8) *(float2*)(orow8 + dc) = make_float2(avD[ntd][2], avD[ntd][3]);
    }
}

// ---------------------------------------------------------------------------
__global__ void __launch_bounds__(256)
attn_win(const float* __restrict__ q, const float* __restrict__ k,
         const float* __restrict__ v, float* attnp, float* outp) {
    float* attn = attnp ? attnp : g_attn_scr;
    float* out  = outp  ? outp  : g_out_scr;
    const int bh = blockIdx.y;
    const int nw = L - g_cnt[bh][0];
    const int widx = blockIdx.x * 8 + (threadIdx.x >> 5);
    if (widx >= nw) return;
    const int lane = threadIdx.x & 31;
    const int i = g_perm[bh][L - 1 - widx];
    const int j0 = max(0, i - WIN), j1 = min(L - 1, i + WIN);
    const int n = j1 - j0 + 1;
    const float* qr = q + ((size_t)bh * L + i) * D;
    float q0 = qr[lane], q1 = qr[lane + 32];
    float p[5], mx = -3.0e38f;
#pragma unroll
    for (int jj = 0; jj < 5; jj++) {
        float sc = -3.0e38f;
        if (jj < n) {
            const float* kr = k + ((size_t)bh * L + j0 + jj) * D;
            float d = q0 * kr[lane] + q1 * kr[lane + 32];
#pragma unroll
            for (int o = 16; o > 0; o >>= 1) d += __shfl_xor_sync(0xffffffffu, d, o);
            sc = d * 0.125f;
        }
        p[jj] = sc; mx = fmaxf(mx, sc);
    }
    float sum = 0.f;
#pragma unroll
    for (int jj = 0; jj < 5; jj++) { p[jj] = (jj < n) ? __expf(p[jj] - mx) : 0.f; sum += p[jj]; }
    float inv = 1.0f / sum;
#pragma unroll
    for (int jj = 0; jj < 5; jj++) p[jj] *= inv;

    float4* arow4 = (float4*)(attn + ((size_t)bh * L + i) * (size_t)L);
    const int s_lo = j0 >> 2, s_hi = j1 >> 2;
#pragma unroll
    for (int it = 0; it < 16; it++) {
        int s4 = lane + it * 32;
        if (s4 < s_lo || s4 > s_hi) arow4[s4] = make_float4(0.f, 0.f, 0.f, 0.f);
    }
    if (lane <= s_hi - s_lo) {
        int s4 = s_lo + lane;
        float vv[4];
#pragma unroll
        for (int e = 0; e < 4; e++) {
            int idx = s4 * 4 + e;
            vv[e] = (idx >= j0 && idx <= j1) ? p[idx - j0] : 0.f;
        }
        arow4[s4] = make_float4(vv[0], vv[1], vv[2], vv[3]);
    }
    float o0 = 0.f, o1 = 0.f;
#pragma unroll
    for (int jj = 0; jj < 5; jj++) {
        if (jj < n) {
            const float* vr = v + ((size_t)bh * L + j0 + jj) * D;
            o0 += p[jj] * vr[lane];
            o1 += p[jj] * vr[lane + 32];
        }
    }
    float* orow = out + ((size_t)bh * L + i) * D;
    orow[lane] = o0; orow[lane + 32] = o1;
}

// ---------------------------------------------------------------------------
extern "C" void kernel_launch(void* const* d_in, const int* in_sizes, int n_in,
                              void* d_out, int out_size) {
    const float* q  = (const float*)d_in[0];
    const float* k  = (const float*)d_in[1];
    const float* v  = (const float*)d_in[2];
    const float* gw = (const float*)d_in[3];
    const float* gb = (const float*)d_in[4];

    const long long OUTE = (long long)BH * L * D;
    const long long ATTE = (long long)BH * L * L;
    float* outp = nullptr; float* attnp = nullptr;
    if ((long long)out_size == OUTE + ATTE) { outp = (float*)d_out; attnp = (float*)d_out + OUTE; }
    else if ((long long)out_size == ATTE)   { attnp = (float*)d_out; }
    else                                    { outp = (float*)d_out; }

    cudaFuncSetAttribute(attn_gated, cudaFuncAttributeMaxDynamicSharedMemorySize, SMEMB);
    gate_init<<<1, 64>>>();
    gate_kernel<<<BH * 8, 256>>>(q, gw, gb);
    attn_gated<<<dim3(L / TQ, BH), 256, SMEMB>>>(q, k, v, attnp, outp);
    attn_win<<<dim3(L / 8, BH), 256>>>(q, k, v, attnp, outp);
}